// round 3
// baseline (speedup 1.0000x reference)
#include <cuda_runtime.h>

#define N_NODES 100000
#define N_EDGES 1250000
#define D 64
#define NPB 64            // nodes per block in fused GEMM
#define SCAN_THREADS 1024
#define CHUNK ((N_NODES + SCAN_THREADS - 1) / SCAN_THREADS)  // 98

// ----- CSR scratch (static device memory: allowed; no allocation) ----------
__device__ int g_counts[N_NODES];
__device__ int g_offsets[N_NODES + 1];
__device__ int g_cursor[N_NODES];
__device__ int g_src[N_EDGES];

// ---------------------------------------------------------------------------
// Edge-index width probe: node ids < 2^31, so for little-endian int64 the odd
// 32-bit words are all zero. Uniform loads -> broadcast, negligible cost.
// ---------------------------------------------------------------------------
__device__ __forceinline__ bool probe_is64(const int* __restrict__ e32) {
    return (e32[1] == 0) && (e32[3] == 0) && (e32[5] == 0) && (e32[7] == 0);
}
__device__ __forceinline__ int load_dst(const int* __restrict__ e32, int e, bool is64) {
    return is64 ? e32[2 * (N_EDGES + e)] : e32[N_EDGES + e];
}
__device__ __forceinline__ int load_src(const int* __restrict__ e32, int e, bool is64) {
    return is64 ? e32[2 * e] : e32[e];
}

// K1: zero the per-node degree counters --------------------------------------
__global__ void zero_counts_kernel() {
    int i = blockIdx.x * blockDim.x + threadIdx.x;
    if (i < N_NODES) g_counts[i] = 0;
}

// K2: degree histogram -------------------------------------------------------
__global__ void hist_kernel(const int* __restrict__ e32) {
    int e = blockIdx.x * blockDim.x + threadIdx.x;
    if (e >= N_EDGES) return;
    bool is64 = probe_is64(e32);
    atomicAdd(&g_counts[load_dst(e32, e, is64)], 1);
}

// K3: single-block exclusive scan over counts -> offsets (+ cursor copy) -----
__global__ void scan_kernel() {
    __shared__ int part[SCAN_THREADS];
    int t = threadIdx.x;
    int begin = t * CHUNK;
    int end   = begin + CHUNK; if (end > N_NODES) end = N_NODES;

    int s = 0;
    for (int i = begin; i < end; i++) s += g_counts[i];
    part[t] = s;
    __syncthreads();

    // Hillis-Steele inclusive scan over the 1024 partials
    for (int off = 1; off < SCAN_THREADS; off <<= 1) {
        int u = (t >= off) ? part[t - off] : 0;
        __syncthreads();
        part[t] += u;
        __syncthreads();
    }

    int running = part[t] - s;  // exclusive prefix for this chunk
    for (int i = begin; i < end; i++) {
        g_offsets[i] = running;
        g_cursor[i]  = running;
        running += g_counts[i];
    }
    if (t == SCAN_THREADS - 1) g_offsets[N_NODES] = part[SCAN_THREADS - 1];
}

// K4: bin edges into CSR (order within a bin is irrelevant for a sum) --------
__global__ void bin_kernel(const int* __restrict__ e32) {
    int e = blockIdx.x * blockDim.x + threadIdx.x;
    if (e >= N_EDGES) return;
    bool is64 = probe_is64(e32);
    int dst = load_dst(e32, e, is64);
    int src = load_src(e32, e, is64);
    int pos = atomicAdd(&g_cursor[dst], 1);
    g_src[pos] = src;
}

// K5: gather-sum: out[node] = sum over CSR neighbors of x[src]. One warp per
// node; lane owns 2 of the 64 features (float2). No atomics, writes once.
// ---------------------------------------------------------------------------
__global__ void gather_kernel(const float* __restrict__ x,
                              float* __restrict__ out) {
    int w    = (blockIdx.x * blockDim.x + threadIdx.x) >> 5;
    int lane = threadIdx.x & 31;
    if (w >= N_NODES) return;

    int start = g_offsets[w];
    int end   = g_offsets[w + 1];

    float2 acc = make_float2(0.f, 0.f);
    for (int j = start; j < end; j += 32) {
        int sid = -1;
        if (j + lane < end) sid = g_src[j + lane];
#pragma unroll
        for (int jj = 0; jj < 32; jj++) {
            int s = __shfl_sync(0xffffffffu, sid, jj);
            if (s >= 0) {
                float2 v = *reinterpret_cast<const float2*>(x + (long long)s * D + lane * 2);
                acc.x += v.x;
                acc.y += v.y;
            }
        }
    }
    *reinterpret_cast<float2*>(out + (long long)w * D + lane * 2) = acc;
}

// K6: fused  out = tanh( [aggr | x] @ [W_l ; W_r] + b ), in place over aggr --
__global__ void fused_gemm_kernel(const float* __restrict__ x,
                                  const float* __restrict__ Wl,
                                  const float* __restrict__ bl,
                                  const float* __restrict__ Wr,
                                  float* __restrict__ out) {
    extern __shared__ float sm[];
    float* sW  = sm;                 // [128][64]: rows 0..63 = W_l, 64..127 = W_r
    float* sAX = sm + 128 * 64;      // [NPB][128]: cols 0..63 = aggr, 64..127 = x
    float* sB  = sAX + NPB * 128;    // [64]

    int tid = threadIdx.x;
    int node0 = blockIdx.x * NPB;

    float4* sW4 = reinterpret_cast<float4*>(sW);
    const float4* Wl4 = reinterpret_cast<const float4*>(Wl);
    const float4* Wr4 = reinterpret_cast<const float4*>(Wr);
#pragma unroll
    for (int i = 0; i < 4; i++) {
        int idx = tid + i * 256;
        sW4[idx]        = Wl4[idx];
        sW4[1024 + idx] = Wr4[idx];
    }
    if (tid < 64) sB[tid] = bl[tid];

    float4* sAX4 = reinterpret_cast<float4*>(sAX);
    for (int i = tid; i < NPB * 32; i += 256) {
        int n = i >> 5;
        int c = i & 31;
        int node = node0 + n;
        float4 v = make_float4(0.f, 0.f, 0.f, 0.f);
        if (node < N_NODES) {
            if (c < 16) v = *reinterpret_cast<const float4*>(out + (long long)node * D + c * 4);
            else        v = *reinterpret_cast<const float4*>(x   + (long long)node * D + (c - 16) * 4);
        }
        sAX4[i] = v;
    }
    __syncthreads();

    int tx = tid & 15;
    int ng = tid >> 4;

    float4 bb = reinterpret_cast<float4*>(sB)[tx];
    float4 acc0 = bb, acc1 = bb, acc2 = bb, acc3 = bb;

    const float* r0 = sAX + (ng * 4 + 0) * 128;
    const float* r1 = sAX + (ng * 4 + 1) * 128;
    const float* r2 = sAX + (ng * 4 + 2) * 128;
    const float* r3 = sAX + (ng * 4 + 3) * 128;

#pragma unroll 8
    for (int k = 0; k < 128; k++) {
        float4 w = sW4[k * 16 + tx];
        float a0 = r0[k], a1 = r1[k], a2 = r2[k], a3 = r3[k];
        acc0.x += a0 * w.x; acc0.y += a0 * w.y; acc0.z += a0 * w.z; acc0.w += a0 * w.w;
        acc1.x += a1 * w.x; acc1.y += a1 * w.y; acc1.z += a1 * w.z; acc1.w += a1 * w.w;
        acc2.x += a2 * w.x; acc2.y += a2 * w.y; acc2.z += a2 * w.z; acc2.w += a2 * w.w;
        acc3.x += a3 * w.x; acc3.y += a3 * w.y; acc3.z += a3 * w.z; acc3.w += a3 * w.w;
    }

    float4 accs[4] = {acc0, acc1, acc2, acc3};
#pragma unroll
    for (int n = 0; n < 4; n++) {
        int node = node0 + ng * 4 + n;
        if (node < N_NODES) {
            float4 a = accs[n];
            a.x = tanhf(a.x); a.y = tanhf(a.y); a.z = tanhf(a.z); a.w = tanhf(a.w);
            *reinterpret_cast<float4*>(out + (long long)node * D + tx * 4) = a;
        }
    }
}

// ---------------------------------------------------------------------------
extern "C" void kernel_launch(void* const* d_in, const int* in_sizes, int n_in,
                              void* d_out, int out_size) {
    const float* x  = (const float*)d_in[0];
    const int*   ei = (const int*)d_in[1];   // int32 or int64, probed on device
    const float* Wl = (const float*)d_in[2];
    const float* bl = (const float*)d_in[3];
    const float* Wr = (const float*)d_in[4];
    float* out = (float*)d_out;

    // CSR build (recomputed every call: deterministic, allocation-free)
    zero_counts_kernel<<<(N_NODES + 255) / 256, 256>>>();
    hist_kernel<<<(N_EDGES + 255) / 256, 256>>>(ei);
    scan_kernel<<<1, SCAN_THREADS>>>();
    bin_kernel<<<(N_EDGES + 255) / 256, 256>>>(ei);

    // Aggregate: out = segment_sum (no atomics, every element overwritten)
    gather_kernel<<<(N_NODES * 32 + 255) / 256, 256>>>(x, out);

    // Fused GEMM + bias + tanh (in place)
    const int smem = (128 * 64 + NPB * 128 + 64) * (int)sizeof(float);  // 65792 B
    static bool attr_set = false;
    if (!attr_set) {
        cudaFuncSetAttribute(fused_gemm_kernel,
                             cudaFuncAttributeMaxDynamicSharedMemorySize, smem);
        attr_set = true;
    }
    fused_gemm_kernel<<<(N_NODES + NPB - 1) / NPB, 256, smem>>>(x, Wl, bl, Wr, out);
}

// round 4
// speedup vs baseline: 2.3620x; 2.3620x over previous
#include <cuda_runtime.h>

#define N_NODES 100000
#define N_EDGES 1250000
#define D 64
#define NPB 64  // nodes per block in the fused GEMM

typedef unsigned long long ull;

#define PACK_F32X2(out, lo, hi) \
    asm("mov.b64 %0, {%1, %2};" : "=l"(out) : "f"(lo), "f"(hi))
#define UNPACK_F32X2(lo, hi, in) \
    asm("mov.b64 {%0, %1}, %2;" : "=f"(lo), "=f"(hi) : "l"(in))
#define FMA_F32X2(d, a, b, c) \
    asm("fma.rn.f32x2 %0, %1, %2, %3;" : "=l"(d) : "l"(a), "l"(b), "l"(c))
#define TANH_APPROX(y, x) \
    asm("tanh.approx.f32 %0, %1;" : "=f"(y) : "f"(x))

// ---------------------------------------------------------------------------
// Kernel 1: zero the aggregation scratch (we reuse d_out as aggr buffer).
// ---------------------------------------------------------------------------
__global__ void zero_kernel(float4* __restrict__ p, int n4) {
    int i = blockIdx.x * blockDim.x + threadIdx.x;
    if (i < n4) p[i] = make_float4(0.f, 0.f, 0.f, 0.f);
}

// ---------------------------------------------------------------------------
// Kernel 2: edge scatter. 16 threads per edge, each handles one float4 chunk
// of the 64-float row: aggr[dst] += x[src], via red.global.add.v4.f32.
// Runtime-detects int64 vs int32 edge_index (JAX x64 ambiguity): node ids are
// < 2^31 so for little-endian int64 the odd 32-bit words are all zero.
// ---------------------------------------------------------------------------
__global__ void scatter_kernel(const float* __restrict__ x,
                               const int* __restrict__ e32,
                               float* __restrict__ aggr) {
    int t = blockIdx.x * blockDim.x + threadIdx.x;
    int e = t >> 4;
    if (e >= N_EDGES) return;
    int c = (t & 15) << 2;  // float offset within row (0,4,...,60)

    bool is64 = (e32[1] == 0) && (e32[3] == 0) && (e32[5] == 0) && (e32[7] == 0);

    int src, dst;
    if (is64) {
        src = e32[2 * e];
        dst = e32[2 * (N_EDGES + e)];
    } else {
        src = e32[e];
        dst = e32[N_EDGES + e];
    }

    float4 v = *reinterpret_cast<const float4*>(x + (long long)src * D + c);
    float* p = aggr + (long long)dst * D + c;
    asm volatile("red.global.add.v4.f32 [%0], {%1,%2,%3,%4};"
                 :: "l"(p), "f"(v.x), "f"(v.y), "f"(v.z), "f"(v.w)
                 : "memory");
}

// ---------------------------------------------------------------------------
// Kernel 3: fused  out = tanh( [aggr | x] @ [W_l ; W_r] + b )  per node,
// in place over the aggr scratch (= d_out). Inner product uses packed
// fma.rn.f32x2 (2 fp32 FMAs per instruction on sm_103a).
//
// Block: 256 threads, thread (tx, ng) computes cols [4tx,4tx+4) of nodes
// ng*4..+3. Shared: W 32KB + staged [aggr|x] 32KB + bias.
// ---------------------------------------------------------------------------
__global__ void fused_gemm_kernel(const float* __restrict__ x,
                                  const float* __restrict__ Wl,
                                  const float* __restrict__ bl,
                                  const float* __restrict__ Wr,
                                  float* __restrict__ out) {
    extern __shared__ float sm[];
    float* sW  = sm;                 // [128][64]: rows 0..63 = W_l, 64..127 = W_r
    float* sAX = sm + 128 * 64;      // [NPB][128]: cols 0..63 = aggr, 64..127 = x
    float* sB  = sAX + NPB * 128;    // [64]

    int tid = threadIdx.x;
    int node0 = blockIdx.x * NPB;

    // --- stage weights ---
    float4* sW4 = reinterpret_cast<float4*>(sW);
    const float4* Wl4 = reinterpret_cast<const float4*>(Wl);
    const float4* Wr4 = reinterpret_cast<const float4*>(Wr);
#pragma unroll
    for (int i = 0; i < 4; i++) {
        int idx = tid + i * 256;
        sW4[idx]        = Wl4[idx];
        sW4[1024 + idx] = Wr4[idx];
    }
    if (tid < 64) sB[tid] = bl[tid];

    // --- stage [aggr | x] rows ---
    float4* sAX4 = reinterpret_cast<float4*>(sAX);
    for (int i = tid; i < NPB * 32; i += 256) {
        int n = i >> 5;
        int c = i & 31;
        int node = node0 + n;
        float4 v = make_float4(0.f, 0.f, 0.f, 0.f);
        if (node < N_NODES) {
            if (c < 16) v = *reinterpret_cast<const float4*>(out + (long long)node * D + c * 4);
            else        v = *reinterpret_cast<const float4*>(x   + (long long)node * D + (c - 16) * 4);
        }
        sAX4[i] = v;
    }
    __syncthreads();

    int tx = tid & 15;
    int ng = tid >> 4;

    // bias, packed as (x,y)(z,w)
    float4 bb = reinterpret_cast<float4*>(sB)[tx];
    ull bxy, bzw;
    PACK_F32X2(bxy, bb.x, bb.y);
    PACK_F32X2(bzw, bb.z, bb.w);
    ull acc[4][2];
#pragma unroll
    for (int n = 0; n < 4; n++) { acc[n][0] = bxy; acc[n][1] = bzw; }

    const float* r0 = sAX + (ng * 4 + 0) * 128;
    const float* r1 = sAX + (ng * 4 + 1) * 128;
    const float* r2 = sAX + (ng * 4 + 2) * 128;
    const float* r3 = sAX + (ng * 4 + 3) * 128;

    // W viewed as packed pairs: element [k*16+tx] -> {(wx,wy),(wz,ww)}
    const ulonglong2* sW2 = reinterpret_cast<const ulonglong2*>(sW);

#pragma unroll 4
    for (int k0 = 0; k0 < 128; k0 += 4) {
        float4 a0 = *reinterpret_cast<const float4*>(r0 + k0);
        float4 a1 = *reinterpret_cast<const float4*>(r1 + k0);
        float4 a2 = *reinterpret_cast<const float4*>(r2 + k0);
        float4 a3 = *reinterpret_cast<const float4*>(r3 + k0);
        const float* ap0 = reinterpret_cast<const float*>(&a0);
        const float* ap1 = reinterpret_cast<const float*>(&a1);
        const float* ap2 = reinterpret_cast<const float*>(&a2);
        const float* ap3 = reinterpret_cast<const float*>(&a3);
#pragma unroll
        for (int kk = 0; kk < 4; kk++) {
            ulonglong2 w = sW2[(k0 + kk) * 16 + tx];
            ull aa0, aa1, aa2, aa3;
            PACK_F32X2(aa0, ap0[kk], ap0[kk]);
            PACK_F32X2(aa1, ap1[kk], ap1[kk]);
            PACK_F32X2(aa2, ap2[kk], ap2[kk]);
            PACK_F32X2(aa3, ap3[kk], ap3[kk]);
            FMA_F32X2(acc[0][0], aa0, w.x, acc[0][0]);
            FMA_F32X2(acc[0][1], aa0, w.y, acc[0][1]);
            FMA_F32X2(acc[1][0], aa1, w.x, acc[1][0]);
            FMA_F32X2(acc[1][1], aa1, w.y, acc[1][1]);
            FMA_F32X2(acc[2][0], aa2, w.x, acc[2][0]);
            FMA_F32X2(acc[2][1], aa2, w.y, acc[2][1]);
            FMA_F32X2(acc[3][0], aa3, w.x, acc[3][0]);
            FMA_F32X2(acc[3][1], aa3, w.y, acc[3][1]);
        }
    }

    // --- tanh (HW approx MUFU) + store ---
#pragma unroll
    for (int n = 0; n < 4; n++) {
        int node = node0 + ng * 4 + n;
        if (node < N_NODES) {
            float4 a;
            UNPACK_F32X2(a.x, a.y, acc[n][0]);
            UNPACK_F32X2(a.z, a.w, acc[n][1]);
            TANH_APPROX(a.x, a.x);
            TANH_APPROX(a.y, a.y);
            TANH_APPROX(a.z, a.z);
            TANH_APPROX(a.w, a.w);
            *reinterpret_cast<float4*>(out + (long long)node * D + tx * 4) = a;
        }
    }
}

// ---------------------------------------------------------------------------
extern "C" void kernel_launch(void* const* d_in, const int* in_sizes, int n_in,
                              void* d_out, int out_size) {
    const float* x  = (const float*)d_in[0];
    const int*   ei = (const int*)d_in[1];   // int32 or int64, probed on device
    const float* Wl = (const float*)d_in[2];
    const float* bl = (const float*)d_in[3];
    const float* Wr = (const float*)d_in[4];
    float* out = (float*)d_out;

    // 1) zero aggr scratch (= d_out)
    int n4 = N_NODES * D / 4;
    zero_kernel<<<(n4 + 255) / 256, 256>>>((float4*)out, n4);

    // 2) edge scatter-add
    int threads = N_EDGES * 16;
    scatter_kernel<<<(threads + 255) / 256, 256>>>(x, ei, out);

    // 3) fused GEMM + bias + tanh (in place)
    const int smem = (128 * 64 + NPB * 128 + 64) * (int)sizeof(float);  // 65792 B
    static bool attr_set = false;
    if (!attr_set) {
        cudaFuncSetAttribute(fused_gemm_kernel,
                             cudaFuncAttributeMaxDynamicSharedMemorySize, smem);
        attr_set = true;
    }
    fused_gemm_kernel<<<(N_NODES + NPB - 1) / NPB, 256, smem>>>(x, Wl, bl, Wr, out);
}